// round 14
// baseline (speedup 1.0000x reference)
#include <cuda_runtime.h>
#include <cuda_bf16.h>
#include <cstdint>

#define Bb 4
#define HWD 1024
#define EPSF 1e-5f

#define SSTR 36            // padded row stride (floats); 144 B => 16B-aligned rows
#define SLICE (32 * SSTR)  // 1152 floats per staged 32x32 slice

typedef unsigned long long ull;

// ---------------- scratch ----------------
__device__ float g_mm  [(size_t)Bb*HWD*HWD];
__device__ float g_mmT [(size_t)Bb*HWD*HWD];
__device__ float g_P   [(size_t)Bb*10*HWD*HWD];
__device__ float g_Q   [(size_t)Bb*10*HWD*HWD];
__device__ float g_P2  [(size_t)Bb*10*HWD*HWD];
__device__ float g_Q2  [(size_t)Bb*10*HWD*HWD];
__device__ float g_y1  [(size_t)Bb*HWD*HWD];
__device__ float g_zT  [(size_t)Bb*HWD*HWD];
__device__ float g_cf  [(size_t)Bb*HWD*HWD];
__device__ float g_attn[(size_t)Bb*HWD*HWD];
__device__ float    g_amax  [Bb*HWD];
__device__ unsigned g_amaxu2[Bb*HWD];
__device__ unsigned g_bmaxu [Bb*HWD];

// ---------------- helpers ----------------
__device__ __forceinline__ unsigned enc_f(float f) {
    unsigned u = __float_as_uint(f);
    return (u & 0x80000000u) ? ~u : (u | 0x80000000u);
}
__device__ __forceinline__ float dec_f(unsigned u) {
    return __uint_as_float((u & 0x80000000u) ? (u & 0x7fffffffu) : ~u);
}

#define PACK2(p, lo, hi)  asm("mov.b64 %0, {%1, %2};" : "=l"(p) : "f"(lo), "f"(hi))
#define UNPACK2(lo, hi, p) asm("mov.b64 {%0, %1}, %2;" : "=f"(lo), "=f"(hi) : "l"(p))
#define FMA2(d, a, w)     asm("fma.rn.f32x2 %0, %1, %2, %3;" : "=l"(d) : "l"(a), "l"(w), "l"(d))

// ---------------- init / max reductions ----------------
__global__ void initb_kernel() {
    int i = blockIdx.x * blockDim.x + threadIdx.x;
    if (i < Bb * HWD) g_bmaxu[i] = 0u;
}
__global__ void initab_kernel() {
    int i = blockIdx.x * blockDim.x + threadIdx.x;
    if (i < Bb * HWD) { g_bmaxu[i] = 0u; g_amaxu2[i] = 0u; }
}

__global__ void rowmax_kernel(const float* __restrict__ p1, float* __restrict__ om) {
    int row = blockIdx.x;
    size_t base = (size_t)row * HWD;
    int tid = threadIdx.x;
    float m = -3.4e38f;
    for (int j = tid; j < HWD; j += 256) m = fmaxf(m, p1[base + j]);
    __shared__ float red[256];
    red[tid] = m; __syncthreads();
    for (int s = 128; s > 0; s >>= 1) {
        if (tid < s) red[tid] = fmaxf(red[tid], red[tid + s]);
        __syncthreads();
    }
    if (tid == 0) om[row] = red[0];
}

__global__ void colmax_kernel(const float* __restrict__ p1) {
    int chunk = blockIdx.x;
    int b = blockIdx.y;
    int i0 = threadIdx.x * 4;
    size_t bb = (size_t)b * HWD * HWD;
    float m0 = -3.4e38f, m1 = -3.4e38f, m2 = -3.4e38f, m3 = -3.4e38f;
    int oBeg = chunk * 128, oEnd = oBeg + 128;
    for (int o = oBeg; o < oEnd; o++) {
        const float4 v = *(const float4*)(p1 + bb + (size_t)o * HWD + i0);
        m0 = fmaxf(m0, v.x); m1 = fmaxf(m1, v.y);
        m2 = fmaxf(m2, v.z); m3 = fmaxf(m3, v.w);
    }
    int ib = b * HWD + i0;
    atomicMax(&g_bmaxu[ib + 0], enc_f(m0));
    atomicMax(&g_bmaxu[ib + 1], enc_f(m1));
    atomicMax(&g_bmaxu[ib + 2], enc_f(m2));
    atomicMax(&g_bmaxu[ib + 3], enc_f(m3));
}

// ---------------- mutual matching #1 ----------------
__global__ void mm_kernel(const float* __restrict__ corr) {
    int to = blockIdx.x, ti = blockIdx.y;
    if (ti < to) return;
    int b = blockIdx.z;
    size_t base = (size_t)b * HWD * HWD;
    __shared__ float s1[32][33], s2[32][33];
    int tx = threadIdx.x, ty0 = threadIdx.y;
    #pragma unroll
    for (int k = 0; k < 4; k++) {
        int y = ty0 + k * 8;
        int o1 = to * 32 + y, i1 = ti * 32 + tx;
        float c1 = corr[base + (size_t)o1 * HWD + i1];
        float v1 = c1 * c1 * c1 /
                   ((g_amax[b * HWD + o1] + EPSF) * (dec_f(g_bmaxu[b * HWD + i1]) + EPSF));
        g_mm[base + (size_t)o1 * HWD + i1] = v1;
        s1[y][tx] = v1;
        int o2 = ti * 32 + y, i2 = to * 32 + tx;
        float c2 = corr[base + (size_t)o2 * HWD + i2];
        float v2 = c2 * c2 * c2 /
                   ((g_amax[b * HWD + o2] + EPSF) * (dec_f(g_bmaxu[b * HWD + i2]) + EPSF));
        g_mm[base + (size_t)o2 * HWD + i2] = v2;
        s2[y][tx] = v2;
    }
    __syncthreads();
    #pragma unroll
    for (int k = 0; k < 4; k++) {
        int y = ty0 + k * 8;
        g_mmT[base + (size_t)(to * 32 + y) * HWD + ti * 32 + tx] = s2[tx][y];
        g_mmT[base + (size_t)(ti * 32 + y) * HWD + to * 32 + tx] = s1[tx][y];
    }
}

// ---------------- fused CenterPivotConv4d layer ----------------
// out[co][o][i] = relu( conv3x3_inner(in; wsp) + conv3x3_outer(in; wq) + b )
// gridDim.y = 2 processes the two symmetric-stack orientations in one launch.
// Each thread computes CPG channels for PPT pixels of one slice-column.
// 16B-aligned slice rows (SSTR=36): STS.128 staging and LDS.128 operand loads.
template <int Ci, int Co, int COG, int W, int THREADS, int MINB>
__global__ void __launch_bounds__(THREADS, MINB) fconv_kernel(
    const float* __restrict__ in0, const float* __restrict__ in1,
    const float* __restrict__ wq, const float* __restrict__ bq,
    const float* __restrict__ wsp, const float* __restrict__ bsp,
    float* __restrict__ out0, float* __restrict__ out1)
{
    constexpr int R   = 3 * (W + 2);
    constexpr int CPG = Co / COG;
    constexpr int KP  = (CPG + 1) / 2;
    constexpr int NW4 = Ci * 9 * COG * KP;
    constexpr int TPG = THREADS / COG;
    constexpr int TPC = TPG / W;            // threads per slice-column
    constexpr int PPT = 1024 / TPC;         // pixels per thread (multiple of 4)
    constexpr int RP  = PPT / 2;
    constexpr int LPR = TPC / 32;           // px-groups per slice row
    static_assert(PPT % 4 == 0, "PPT must be multiple of 4");

    extern __shared__ unsigned char smraw[];
    ulonglong2* wq4 = (ulonglong2*)smraw;   // [NW4] {pair(co0),pair(co1)}
    ulonglong2* ws4 = wq4 + NW4;
    float* bsum = (float*)(ws4 + NW4);
    float* rows = bsum + ((Co + 3) & ~3);   // [R][SLICE], 16B-aligned

    const float* in  = blockIdx.y ? in1  : in0;
    float*       out = blockIdx.y ? out1 : out0;
    int tid = threadIdx.x;

    for (int idx = tid; idx < 2 * NW4; idx += THREADS) {
        int r = idx % NW4;
        const float* wsrc = (idx < NW4) ? wq : wsp;
        ulonglong2* wdst  = (idx < NW4) ? wq4 : ws4;
        int k  = r % KP;
        int g  = (r / KP) % COG;
        int tp = (r / (KP * COG)) % 9;
        int ci = r / (KP * COG * 9);
        int co0 = g * CPG + 2 * k;
        int co1 = co0 + 1; if (co1 > g * CPG + CPG - 1) co1 = co0;
        float a0 = wsrc[(co0 * Ci + ci) * 9 + tp];
        float a1 = wsrc[(co1 * Ci + ci) * 9 + tp];
        ull p0, p1; PACK2(p0, a0, a0); PACK2(p1, a1, a1);
        wdst[r] = make_ulonglong2(p0, p1);
    }
    if (tid < Co) bsum[tid] = bq[tid] + bsp[tid];

    constexpr int BPB = 1024 / W;
    int blk = blockIdx.x;
    int b   = blk / BPB;
    int rem = blk - b * BPB;
    int h   = rem / (32 / W);
    int w0  = (rem - h * (32 / W)) * W;

    int cgrp = tid / TPG;
    int lt   = tid % TPG;
    int c    = lt / TPC;
    int sub  = lt % TPC;
    int py   = sub / LPR;
    int px0  = (sub % LPR) * PPT;

    ull acc[CPG][RP];
    #pragma unroll
    for (int l = 0; l < CPG; l++)
        #pragma unroll
        for (int rp = 0; rp < RP; rp++) acc[l][rp] = 0ull;

    for (int ci = 0; ci < Ci; ci++) {
        __syncthreads();
        size_t cBase = ((size_t)(b * Ci + ci)) << 20;
        for (int idx = tid; idx < R * 256; idx += THREADS) {
            int k = idx >> 8; int j = idx & 255;
            int ry = k / (W + 2); int rx = k - ry * (W + 2);
            int ny = h - 1 + ry, nx = w0 - 1 + rx;
            float4 v = make_float4(0.f, 0.f, 0.f, 0.f);
            if ((unsigned)ny < 32u && (unsigned)nx < 32u)
                v = *(const float4*)(in + cBase + ((size_t)(ny * 32 + nx) << 10) + (j << 2));
            int irow = j >> 3, icol = (j & 7) << 2;
            *(float4*)(rows + k * SLICE + irow * SSTR + icol) = v;   // STS.128
        }
        __syncthreads();

        // ---- inner 3x3 conv (support dims) on the center slice ----
        const float* cr0 = rows + ((W + 2) + (c + 1)) * SLICE;
        #pragma unroll
        for (int dy = 0; dy < 3; dy++) {
            int iy = py + dy - 1;
            float t[PPT + 2];
            if ((unsigned)iy < 32u) {
                const float* cr = cr0 + iy * SSTR;
                #pragma unroll
                for (int q = 0; q < PPT / 4; q++) {
                    float4 vv = *(const float4*)(cr + px0 + 4 * q);   // LDS.128
                    t[1 + 4 * q] = vv.x; t[2 + 4 * q] = vv.y;
                    t[3 + 4 * q] = vv.z; t[4 + 4 * q] = vv.w;
                }
                t[0]       = (px0 > 0)        ? cr[px0 - 1]   : 0.f;
                t[PPT + 1] = (px0 + PPT < 32) ? cr[px0 + PPT] : 0.f;
            } else {
                #pragma unroll
                for (int jj = 0; jj < PPT + 2; jj++) t[jj] = 0.f;
            }
            ull pr[PPT + 1];
            #pragma unroll
            for (int i = 0; i < PPT + 1; i++) PACK2(pr[i], t[i], t[i + 1]);
            #pragma unroll
            for (int dx = 0; dx < 3; dx++) {
                const ulonglong2* wp = ws4 + ((ci * 9 + dy * 3 + dx) * COG + cgrp) * KP;
                #pragma unroll
                for (int k = 0; k < KP; k++) {
                    ulonglong2 wv = wp[k];
                    #pragma unroll
                    for (int rp = 0; rp < RP; rp++)
                        FMA2(acc[2 * k][rp], pr[dx + 2 * rp], wv.x);
                    if (2 * k + 1 < CPG) {
                        #pragma unroll
                        for (int rp = 0; rp < RP; rp++)
                            FMA2(acc[2 * k + 1][rp], pr[dx + 2 * rp], wv.y);
                    }
                }
            }
        }
        // ---- outer 3x3 conv (query dims): same pixels from the 9 neighbor slices ----
        #pragma unroll
        for (int ky = 0; ky < 3; ky++) {
            #pragma unroll
            for (int kx = 0; kx < 3; kx++) {
                const ulonglong2* up = (const ulonglong2*)(rows
                    + (ky * (W + 2) + c + kx) * SLICE + py * SSTR + px0);
                ull u[RP];
                #pragma unroll
                for (int rp = 0; rp < RP; rp += 2) {
                    ulonglong2 uu = up[rp >> 1];                      // LDS.128
                    u[rp] = uu.x; u[rp + 1] = uu.y;
                }
                const ulonglong2* wp = wq4 + ((ci * 9 + ky * 3 + kx) * COG + cgrp) * KP;
                #pragma unroll
                for (int k = 0; k < KP; k++) {
                    ulonglong2 wv = wp[k];
                    #pragma unroll
                    for (int rp = 0; rp < RP; rp++)
                        FMA2(acc[2 * k][rp], u[rp], wv.x);
                    if (2 * k + 1 < CPG) {
                        #pragma unroll
                        for (int rp = 0; rp < RP; rp++)
                            FMA2(acc[2 * k + 1][rp], u[rp], wv.y);
                    }
                }
            }
        }
    }

    // ---- epilogue: bias + relu, vectorized store ----
    #pragma unroll
    for (int l = 0; l < CPG; l++) {
        int co = cgrp * CPG + l;
        float bsc = bsum[co];
        float o[PPT];
        #pragma unroll
        for (int rp = 0; rp < RP; rp++) {
            float lo, hi; UNPACK2(lo, hi, acc[l][rp]);
            o[2 * rp]     = fmaxf(lo + bsc, 0.f);
            o[2 * rp + 1] = fmaxf(hi + bsc, 0.f);
        }
        float* ob = out + (((size_t)(b * Co + co)) << 20)
                    + ((size_t)(h * 32 + w0 + c) << 10) + py * 32 + px0;
        #pragma unroll
        for (int q = 0; q < PPT; q += 4)
            *(float4*)(ob + q) = make_float4(o[q], o[q + 1], o[q + 2], o[q + 3]);
    }
}

// ---------------- cf = y1 + T(zT), fused with phase-2 row/col maxes ----------------
__global__ void transadd_kernel(const float* __restrict__ y1, const float* __restrict__ zT,
                                float* __restrict__ cf) {
    int to = blockIdx.x, ti = blockIdx.y, b = blockIdx.z;
    size_t base = (size_t)b << 20;
    __shared__ float s[32][33];
    __shared__ unsigned cred[8][32];
    int tx = threadIdx.x, ty0 = threadIdx.y;
    #pragma unroll
    for (int k = 0; k < 4; k++) {
        int y = ty0 + k * 8;
        s[y][tx] = zT[base + ((size_t)(ti * 32 + y) << 10) + to * 32 + tx];
    }
    __syncthreads();
    float v[4];
    #pragma unroll
    for (int k = 0; k < 4; k++) {
        int y = ty0 + k * 8;
        size_t idx = base + ((size_t)(to * 32 + y) << 10) + ti * 32 + tx;
        v[k] = y1[idx] + s[tx][y];
        cf[idx] = v[k];
    }
    #pragma unroll
    for (int k = 0; k < 4; k++) {
        float m = v[k];
        #pragma unroll
        for (int off = 16; off; off >>= 1)
            m = fmaxf(m, __shfl_xor_sync(0xffffffffu, m, off));
        if (tx == 0)
            atomicMax(&g_amaxu2[b * HWD + to * 32 + ty0 + k * 8], enc_f(m));
    }
    float cm = fmaxf(fmaxf(v[0], v[1]), fmaxf(v[2], v[3]));
    cred[ty0][tx] = enc_f(cm);
    __syncthreads();
    if (ty0 == 0) {
        unsigned m = cred[0][tx];
        #pragma unroll
        for (int w = 1; w < 8; w++) m = max(m, cred[w][tx]);
        atomicMax(&g_bmaxu[b * HWD + ti * 32 + tx], m);
    }
}

// ---------------- mutual matching #2 + mask + softmax ----------------
__global__ void softmax_kernel(const float* __restrict__ cf, const int* __restrict__ mask) {
    int row = blockIdx.x;
    int b = row >> 10;
    size_t base = (size_t)row * HWD;
    __shared__ float vals[1024];
    __shared__ float red[256];
    int tid = threadIdx.x;
    float am = dec_f(g_amaxu2[row]) + EPSF;
    float lm = -3.4e38f;
    for (int j = tid; j < HWD; j += 256) {
        float c = cf[base + j];
        float bm = dec_f(g_bmaxu[(b << 10) + j]) + EPSF;
        float v = c * c * c / (am * bm);
        if (mask[(b << 10) + j] != 0) v = 1e-4f;
        v *= 3.0f;
        vals[j] = v;
        lm = fmaxf(lm, v);
    }
    red[tid] = lm; __syncthreads();
    for (int s = 128; s > 0; s >>= 1) {
        if (tid < s) red[tid] = fmaxf(red[tid], red[tid + s]);
        __syncthreads();
    }
    float m = red[0];
    __syncthreads();
    float ls = 0.f;
    for (int j = tid; j < HWD; j += 256) {
        float e = __expf(vals[j] - m);
        vals[j] = e;
        ls += e;
    }
    red[tid] = ls; __syncthreads();
    for (int s = 128; s > 0; s >>= 1) {
        if (tid < s) red[tid] += red[tid + s];
        __syncthreads();
    }
    float inv = 1.f / red[0];
    __syncthreads();
    for (int j = tid; j < HWD; j += 256)
        g_attn[base + j] = vals[j] * inv;
}

// ---------------- out[b,c,q] = sum_k v[b,c,k] * attn[b,q,k] ----------------
__global__ void __launch_bounds__(256) gemm_kernel(const float* __restrict__ v,
                                                   float* __restrict__ out) {
    __shared__ __align__(16) float Vs[16][68];
    __shared__ __align__(16) float As[16][68];
    int b = blockIdx.z;
    int cT = blockIdx.x * 64;
    int qT = blockIdx.y * 64;
    int tid = threadIdx.x;
    int tx = tid & 15, ty = tid >> 4;
    ull acc2[4][2];
    #pragma unroll
    for (int i = 0; i < 4; i++) { acc2[i][0] = 0ull; acc2[i][1] = 0ull; }
    const float* vb = v + (size_t)b * 256 * 1024;
    const float* ab = g_attn + (size_t)b * HWD * HWD;
    for (int k0 = 0; k0 < 1024; k0 += 16) {
        #pragma unroll
        for (int i = 0; i < 4; i++) {
            int idx = tid + i * 256;
            int kk = idx & 15, cc = idx >> 4;
            Vs[kk][cc] = vb[(size_t)(cT + cc) * 1024 + k0 + kk];
            As[kk][cc] = ab[(size_t)(qT + cc) * HWD + k0 + kk];
        }
        __syncthreads();
        #pragma unroll
        for (int kk = 0; kk < 16; kk++) {
            float4 a4 = *(const float4*)&Vs[kk][ty * 4];
            const ull* bp = (const ull*)&As[kk][tx * 4];
            ull b0 = bp[0], b1 = bp[1];
            float a[4] = {a4.x, a4.y, a4.z, a4.w};
            #pragma unroll
            for (int i = 0; i < 4; i++) {
                ull ad; PACK2(ad, a[i], a[i]);
                FMA2(acc2[i][0], b0, ad);
                FMA2(acc2[i][1], b1, ad);
            }
        }
        __syncthreads();
    }
    #pragma unroll
    for (int i = 0; i < 4; i++) {
        float r0, r1, r2, r3;
        UNPACK2(r0, r1, acc2[i][0]);
        UNPACK2(r2, r3, acc2[i][1]);
        *(float4*)(out + (size_t)(b * 256 + cT + ty * 4 + i) * 1024 + qT + tx * 4)
            = make_float4(r0, r1, r2, r3);
    }
}

// ---------------- host launch ----------------
static inline int fconv_smem(int Ci, int Co, int COG, int W) {
    int cpg = Co / COG, kp = (cpg + 1) / 2;
    int nw4 = Ci * 9 * COG * kp;
    return 2 * nw4 * 16 + ((Co + 3) & ~3) * 4 + 3 * (W + 2) * SLICE * 4;
}

extern "C" void kernel_launch(void* const* d_in, const int* in_sizes, int n_in,
                              void* d_out, int out_size) {
    const float* corr = (const float*)d_in[0];
    const float* v    = (const float*)d_in[1];
    const int*   mask = (const int*)d_in[2];
    const float* wq[3] = {(const float*)d_in[3],  (const float*)d_in[7],  (const float*)d_in[11]};
    const float* bq[3] = {(const float*)d_in[4],  (const float*)d_in[8],  (const float*)d_in[12]};
    const float* ws[3] = {(const float*)d_in[5],  (const float*)d_in[9],  (const float*)d_in[13]};
    const float* bs[3] = {(const float*)d_in[6],  (const float*)d_in[10], (const float*)d_in[14]};
    float* out = (float*)d_out;

    float *p_mm, *p_mmT, *p_P, *p_Q, *p_P2, *p_Q2, *p_y1, *p_zT, *p_cf, *p_amax;
    cudaGetSymbolAddress((void**)&p_mm,  g_mm);
    cudaGetSymbolAddress((void**)&p_mmT, g_mmT);
    cudaGetSymbolAddress((void**)&p_P,   g_P);
    cudaGetSymbolAddress((void**)&p_Q,   g_Q);
    cudaGetSymbolAddress((void**)&p_P2,  g_P2);
    cudaGetSymbolAddress((void**)&p_Q2,  g_Q2);
    cudaGetSymbolAddress((void**)&p_y1,  g_y1);
    cudaGetSymbolAddress((void**)&p_zT,  g_zT);
    cudaGetSymbolAddress((void**)&p_cf,  g_cf);
    cudaGetSymbolAddress((void**)&p_amax, g_amax);

    const int sm110  = fconv_smem(1, 10, 1, 1);
    const int sm1010 = fconv_smem(10, 10, 2, 1);
    const int sm101  = fconv_smem(10, 1, 1, 4);
    cudaFuncSetAttribute((fconv_kernel<1, 10, 1, 1, 256, 3>),
                         cudaFuncAttributeMaxDynamicSharedMemorySize, sm110);
    cudaFuncSetAttribute((fconv_kernel<10, 10, 2, 1, 512, 2>),
                         cudaFuncAttributeMaxDynamicSharedMemorySize, sm1010);
    cudaFuncSetAttribute((fconv_kernel<10, 1, 1, 4, 256, 2>),
                         cudaFuncAttributeMaxDynamicSharedMemorySize, sm101);

    dim3 tile32(32, 8);
    dim3 gridTiles(32, 32, Bb);

    // ---- mutual matching #1 ----
    initb_kernel<<<16, 256>>>();
    rowmax_kernel<<<Bb * HWD, 256>>>(corr, p_amax);
    colmax_kernel<<<dim3(8, Bb), 256>>>(corr);
    mm_kernel<<<gridTiles, tile32>>>(corr);

    // ---- both symmetric stacks per layer in one launch (gridDim.y = 2) ----
    fconv_kernel<1, 10, 1, 1, 256, 3> <<<dim3(Bb * 1024, 2), 256, sm110 >>>(
        p_mm, p_mmT, wq[0], bq[0], ws[0], bs[0], p_P, p_P2);
    fconv_kernel<10, 10, 2, 1, 512, 2><<<dim3(Bb * 1024, 2), 512, sm1010>>>(
        p_P, p_P2, wq[1], bq[1], ws[1], bs[1], p_Q, p_Q2);
    fconv_kernel<10, 1, 1, 4, 256, 2> <<<dim3(Bb * 256, 2),  256, sm101 >>>(
        p_Q, p_Q2, wq[2], bq[2], ws[2], bs[2], p_y1, p_zT);

    // ---- cf = y1 + T(zT) fused with phase-2 maxes ----
    initab_kernel<<<16, 256>>>();
    transadd_kernel<<<gridTiles, tile32>>>(p_y1, p_zT, p_cf);

    // ---- masked softmax ----
    softmax_kernel<<<Bb * HWD, 256>>>(p_cf, mask);

    // ---- weighted sum: out = v @ attn^T ----
    gemm_kernel<<<dim3(4, 16, Bb), 256>>>(v, out);
}

// round 15
// speedup vs baseline: 1.1287x; 1.1287x over previous
#include <cuda_runtime.h>
#include <cuda_bf16.h>
#include <cstdint>

#define Bb 4
#define HWD 1024
#define EPSF 1e-5f

#define SSTR 36            // padded row stride (floats); 144 B => 16B-aligned rows
#define SLICE (32 * SSTR)  // 1152 floats per staged 32x32 slice

typedef unsigned long long ull;

// ---------------- scratch ----------------
__device__ float g_mm  [(size_t)Bb*HWD*HWD];
__device__ float g_mmT [(size_t)Bb*HWD*HWD];
__device__ float g_P   [(size_t)Bb*10*HWD*HWD];
__device__ float g_Q   [(size_t)Bb*10*HWD*HWD];
__device__ float g_P2  [(size_t)Bb*10*HWD*HWD];
__device__ float g_Q2  [(size_t)Bb*10*HWD*HWD];
__device__ float g_y1  [(size_t)Bb*HWD*HWD];
__device__ float g_zT  [(size_t)Bb*HWD*HWD];
__device__ float g_cf  [(size_t)Bb*HWD*HWD];
__device__ float g_attn[(size_t)Bb*HWD*HWD];
__device__ float    g_amax  [Bb*HWD];
__device__ unsigned g_amaxu2[Bb*HWD];
__device__ unsigned g_bmaxu [Bb*HWD];

// ---------------- helpers ----------------
__device__ __forceinline__ unsigned enc_f(float f) {
    unsigned u = __float_as_uint(f);
    return (u & 0x80000000u) ? ~u : (u | 0x80000000u);
}
__device__ __forceinline__ float dec_f(unsigned u) {
    return __uint_as_float((u & 0x80000000u) ? (u & 0x7fffffffu) : ~u);
}

#define PACK2(p, lo, hi)  asm("mov.b64 %0, {%1, %2};" : "=l"(p) : "f"(lo), "f"(hi))
#define UNPACK2(lo, hi, p) asm("mov.b64 {%0, %1}, %2;" : "=f"(lo), "=f"(hi) : "l"(p))
#define FMA2(d, a, w)     asm("fma.rn.f32x2 %0, %1, %2, %3;" : "=l"(d) : "l"(a), "l"(w), "l"(d))

// ---------------- init / max reductions ----------------
__global__ void initb_kernel() {
    int i = blockIdx.x * blockDim.x + threadIdx.x;
    if (i < Bb * HWD) g_bmaxu[i] = 0u;
}
__global__ void initab_kernel() {
    int i = blockIdx.x * blockDim.x + threadIdx.x;
    if (i < Bb * HWD) { g_bmaxu[i] = 0u; g_amaxu2[i] = 0u; }
}

// fused phase-1 row & column maxes: one pass over corr.
// grid (8, Bb), 256 threads. Each block covers 128 rows x all 1024 cols, so row
// maxes are complete (written directly); col maxes accumulate via atomicMax.
__global__ void rowcolmax_kernel(const float* __restrict__ p1, float* __restrict__ om) {
    int chunk = blockIdx.x;
    int b = blockIdx.y;
    int tid = threadIdx.x;
    int warp = tid >> 5, lane = tid & 31;
    int c0 = warp * 128 + lane * 4;          // 8 warps x 128 cols = full 1024
    size_t bb = (size_t)b << 20;
    int oBeg = chunk * 128;
    __shared__ float rpart[128][9];          // [row][warp] partial row maxes
    float m0 = -3.4e38f, m1 = -3.4e38f, m2 = -3.4e38f, m3 = -3.4e38f;
    #pragma unroll 1
    for (int r = 0; r < 128; r++) {
        const float4 v = *(const float4*)(p1 + bb + ((size_t)(oBeg + r) << 10) + c0);
        m0 = fmaxf(m0, v.x); m1 = fmaxf(m1, v.y);
        m2 = fmaxf(m2, v.z); m3 = fmaxf(m3, v.w);
        float rm = fmaxf(fmaxf(v.x, v.y), fmaxf(v.z, v.w));
        #pragma unroll
        for (int off = 16; off; off >>= 1)
            rm = fmaxf(rm, __shfl_xor_sync(0xffffffffu, rm, off));
        if (lane == 0) rpart[r][warp] = rm;
    }
    int ib = b * HWD + c0;
    atomicMax(&g_bmaxu[ib + 0], enc_f(m0));
    atomicMax(&g_bmaxu[ib + 1], enc_f(m1));
    atomicMax(&g_bmaxu[ib + 2], enc_f(m2));
    atomicMax(&g_bmaxu[ib + 3], enc_f(m3));
    __syncthreads();
    if (tid < 128) {
        float m = rpart[tid][0];
        #pragma unroll
        for (int w = 1; w < 8; w++) m = fmaxf(m, rpart[tid][w]);
        om[b * HWD + oBeg + tid] = m;
    }
}

// ---------------- mutual matching #1 ----------------
__global__ void mm_kernel(const float* __restrict__ corr) {
    int to = blockIdx.x, ti = blockIdx.y;
    if (ti < to) return;
    int b = blockIdx.z;
    size_t base = (size_t)b * HWD * HWD;
    __shared__ float s1[32][33], s2[32][33];
    int tx = threadIdx.x, ty0 = threadIdx.y;
    #pragma unroll
    for (int k = 0; k < 4; k++) {
        int y = ty0 + k * 8;
        int o1 = to * 32 + y, i1 = ti * 32 + tx;
        float c1 = corr[base + (size_t)o1 * HWD + i1];
        float v1 = c1 * c1 * c1 /
                   ((g_amax[b * HWD + o1] + EPSF) * (dec_f(g_bmaxu[b * HWD + i1]) + EPSF));
        g_mm[base + (size_t)o1 * HWD + i1] = v1;
        s1[y][tx] = v1;
        int o2 = ti * 32 + y, i2 = to * 32 + tx;
        float c2 = corr[base + (size_t)o2 * HWD + i2];
        float v2 = c2 * c2 * c2 /
                   ((g_amax[b * HWD + o2] + EPSF) * (dec_f(g_bmaxu[b * HWD + i2]) + EPSF));
        g_mm[base + (size_t)o2 * HWD + i2] = v2;
        s2[y][tx] = v2;
    }
    __syncthreads();
    #pragma unroll
    for (int k = 0; k < 4; k++) {
        int y = ty0 + k * 8;
        g_mmT[base + (size_t)(to * 32 + y) * HWD + ti * 32 + tx] = s2[tx][y];
        g_mmT[base + (size_t)(ti * 32 + y) * HWD + to * 32 + tx] = s1[tx][y];
    }
}

// ---------------- fused CenterPivotConv4d layer (R12 best config) ----------------
// out[co][o][i] = relu( conv3x3_inner(in; wsp) + conv3x3_outer(in; wq) + b )
// gridDim.y = 2 processes the two symmetric-stack orientations in one launch.
template <int Ci, int Co, int COG, int W, int THREADS, int MINB>
__global__ void __launch_bounds__(THREADS, MINB) fconv_kernel(
    const float* __restrict__ in0, const float* __restrict__ in1,
    const float* __restrict__ wq, const float* __restrict__ bq,
    const float* __restrict__ wsp, const float* __restrict__ bsp,
    float* __restrict__ out0, float* __restrict__ out1)
{
    constexpr int R   = 3 * (W + 2);
    constexpr int CPG = Co / COG;
    constexpr int KP  = (CPG + 1) / 2;
    constexpr int NW4 = Ci * 9 * COG * KP;
    constexpr int TPG = THREADS / COG;
    constexpr int TPC = TPG / W;            // threads per slice-column
    constexpr int PPT = 1024 / TPC;         // pixels per thread (multiple of 4)
    constexpr int RP  = PPT / 2;
    constexpr int LPR = TPC / 32;           // px-groups per slice row
    static_assert(PPT % 4 == 0, "PPT must be multiple of 4");

    extern __shared__ unsigned char smraw[];
    ulonglong2* wq4 = (ulonglong2*)smraw;   // [NW4] {pair(co0),pair(co1)}
    ulonglong2* ws4 = wq4 + NW4;
    float* bsum = (float*)(ws4 + NW4);
    float* rows = bsum + ((Co + 3) & ~3);   // [R][SLICE], 16B-aligned

    const float* in  = blockIdx.y ? in1  : in0;
    float*       out = blockIdx.y ? out1 : out0;
    int tid = threadIdx.x;

    for (int idx = tid; idx < 2 * NW4; idx += THREADS) {
        int r = idx % NW4;
        const float* wsrc = (idx < NW4) ? wq : wsp;
        ulonglong2* wdst  = (idx < NW4) ? wq4 : ws4;
        int k  = r % KP;
        int g  = (r / KP) % COG;
        int tp = (r / (KP * COG)) % 9;
        int ci = r / (KP * COG * 9);
        int co0 = g * CPG + 2 * k;
        int co1 = co0 + 1; if (co1 > g * CPG + CPG - 1) co1 = co0;
        float a0 = wsrc[(co0 * Ci + ci) * 9 + tp];
        float a1 = wsrc[(co1 * Ci + ci) * 9 + tp];
        ull p0, p1; PACK2(p0, a0, a0); PACK2(p1, a1, a1);
        wdst[r] = make_ulonglong2(p0, p1);
    }
    if (tid < Co) bsum[tid] = bq[tid] + bsp[tid];

    constexpr int BPB = 1024 / W;
    int blk = blockIdx.x;
    int b   = blk / BPB;
    int rem = blk - b * BPB;
    int h   = rem / (32 / W);
    int w0  = (rem - h * (32 / W)) * W;

    int cgrp = tid / TPG;
    int lt   = tid % TPG;
    int c    = lt / TPC;
    int sub  = lt % TPC;
    int py   = sub / LPR;
    int px0  = (sub % LPR) * PPT;

    ull acc[CPG][RP];
    #pragma unroll
    for (int l = 0; l < CPG; l++)
        #pragma unroll
        for (int rp = 0; rp < RP; rp++) acc[l][rp] = 0ull;

    for (int ci = 0; ci < Ci; ci++) {
        __syncthreads();
        size_t cBase = ((size_t)(b * Ci + ci)) << 20;
        for (int idx = tid; idx < R * 256; idx += THREADS) {
            int k = idx >> 8; int j = idx & 255;
            int ry = k / (W + 2); int rx = k - ry * (W + 2);
            int ny = h - 1 + ry, nx = w0 - 1 + rx;
            float4 v = make_float4(0.f, 0.f, 0.f, 0.f);
            if ((unsigned)ny < 32u && (unsigned)nx < 32u)
                v = *(const float4*)(in + cBase + ((size_t)(ny * 32 + nx) << 10) + (j << 2));
            int irow = j >> 3, icol = (j & 7) << 2;
            *(float4*)(rows + k * SLICE + irow * SSTR + icol) = v;   // STS.128
        }
        __syncthreads();

        // ---- inner 3x3 conv (support dims) on the center slice ----
        const float* cr0 = rows + ((W + 2) + (c + 1)) * SLICE;
        #pragma unroll
        for (int dy = 0; dy < 3; dy++) {
            int iy = py + dy - 1;
            float t[PPT + 2];
            if ((unsigned)iy < 32u) {
                const float* cr = cr0 + iy * SSTR;
                #pragma unroll
                for (int q = 0; q < PPT / 4; q++) {
                    float4 vv = *(const float4*)(cr + px0 + 4 * q);   // LDS.128
                    t[1 + 4 * q] = vv.x; t[2 + 4 * q] = vv.y;
                    t[3 + 4 * q] = vv.z; t[4 + 4 * q] = vv.w;
                }
                t[0]       = (px0 > 0)        ? cr[px0 - 1]   : 0.f;
                t[PPT + 1] = (px0 + PPT < 32) ? cr[px0 + PPT] : 0.f;
            } else {
                #pragma unroll
                for (int jj = 0; jj < PPT + 2; jj++) t[jj] = 0.f;
            }
            ull pr[PPT + 1];
            #pragma unroll
            for (int i = 0; i < PPT + 1; i++) PACK2(pr[i], t[i], t[i + 1]);
            #pragma unroll
            for (int dx = 0; dx < 3; dx++) {
                const ulonglong2* wp = ws4 + ((ci * 9 + dy * 3 + dx) * COG + cgrp) * KP;
                #pragma unroll
                for (int k = 0; k < KP; k++) {
                    ulonglong2 wv = wp[k];
                    #pragma unroll
                    for (int rp = 0; rp < RP; rp++)
                        FMA2(acc[2 * k][rp], pr[dx + 2 * rp], wv.x);
                    if (2 * k + 1 < CPG) {
                        #pragma unroll
                        for (int rp = 0; rp < RP; rp++)
                            FMA2(acc[2 * k + 1][rp], pr[dx + 2 * rp], wv.y);
                    }
                }
            }
        }
        // ---- outer 3x3 conv (query dims): same pixels from the 9 neighbor slices ----
        #pragma unroll
        for (int ky = 0; ky < 3; ky++) {
            #pragma unroll
            for (int kx = 0; kx < 3; kx++) {
                const ulonglong2* up = (const ulonglong2*)(rows
                    + (ky * (W + 2) + c + kx) * SLICE + py * SSTR + px0);
                ull u[RP];
                #pragma unroll
                for (int rp = 0; rp < RP; rp += 2) {
                    ulonglong2 uu = up[rp >> 1];                      // LDS.128
                    u[rp] = uu.x; u[rp + 1] = uu.y;
                }
                const ulonglong2* wp = wq4 + ((ci * 9 + ky * 3 + kx) * COG + cgrp) * KP;
                #pragma unroll
                for (int k = 0; k < KP; k++) {
                    ulonglong2 wv = wp[k];
                    #pragma unroll
                    for (int rp = 0; rp < RP; rp++)
                        FMA2(acc[2 * k][rp], u[rp], wv.x);
                    if (2 * k + 1 < CPG) {
                        #pragma unroll
                        for (int rp = 0; rp < RP; rp++)
                            FMA2(acc[2 * k + 1][rp], u[rp], wv.y);
                    }
                }
            }
        }
    }

    // ---- epilogue: bias + relu, vectorized store ----
    #pragma unroll
    for (int l = 0; l < CPG; l++) {
        int co = cgrp * CPG + l;
        float bsc = bsum[co];
        float o[PPT];
        #pragma unroll
        for (int rp = 0; rp < RP; rp++) {
            float lo, hi; UNPACK2(lo, hi, acc[l][rp]);
            o[2 * rp]     = fmaxf(lo + bsc, 0.f);
            o[2 * rp + 1] = fmaxf(hi + bsc, 0.f);
        }
        float* ob = out + (((size_t)(b * Co + co)) << 20)
                    + ((size_t)(h * 32 + w0 + c) << 10) + py * 32 + px0;
        #pragma unroll
        for (int q = 0; q < PPT; q += 4)
            *(float4*)(ob + q) = make_float4(o[q], o[q + 1], o[q + 2], o[q + 3]);
    }
}

// ---------------- cf = y1 + T(zT), fused with phase-2 row/col maxes ----------------
__global__ void transadd_kernel(const float* __restrict__ y1, const float* __restrict__ zT,
                                float* __restrict__ cf) {
    int to = blockIdx.x, ti = blockIdx.y, b = blockIdx.z;
    size_t base = (size_t)b << 20;
    __shared__ float s[32][33];
    __shared__ unsigned cred[8][32];
    int tx = threadIdx.x, ty0 = threadIdx.y;
    #pragma unroll
    for (int k = 0; k < 4; k++) {
        int y = ty0 + k * 8;
        s[y][tx] = zT[base + ((size_t)(ti * 32 + y) << 10) + to * 32 + tx];
    }
    __syncthreads();
    float v[4];
    #pragma unroll
    for (int k = 0; k < 4; k++) {
        int y = ty0 + k * 8;
        size_t idx = base + ((size_t)(to * 32 + y) << 10) + ti * 32 + tx;
        v[k] = y1[idx] + s[tx][y];
        cf[idx] = v[k];
    }
    #pragma unroll
    for (int k = 0; k < 4; k++) {
        float m = v[k];
        #pragma unroll
        for (int off = 16; off; off >>= 1)
            m = fmaxf(m, __shfl_xor_sync(0xffffffffu, m, off));
        if (tx == 0)
            atomicMax(&g_amaxu2[b * HWD + to * 32 + ty0 + k * 8], enc_f(m));
    }
    float cm = fmaxf(fmaxf(v[0], v[1]), fmaxf(v[2], v[3]));
    cred[ty0][tx] = enc_f(cm);
    __syncthreads();
    if (ty0 == 0) {
        unsigned m = cred[0][tx];
        #pragma unroll
        for (int w = 1; w < 8; w++) m = max(m, cred[w][tx]);
        atomicMax(&g_bmaxu[b * HWD + ti * 32 + tx], m);
    }
}

// ---------------- mutual matching #2 + mask + softmax ----------------
__global__ void softmax_kernel(const float* __restrict__ cf, const int* __restrict__ mask) {
    int row = blockIdx.x;
    int b = row >> 10;
    size_t base = (size_t)row * HWD;
    __shared__ float vals[1024];
    __shared__ float red[256];
    int tid = threadIdx.x;
    float am = dec_f(g_amaxu2[row]) + EPSF;
    float lm = -3.4e38f;
    for (int j = tid; j < HWD; j += 256) {
        float c = cf[base + j];
        float bm = dec_f(g_bmaxu[(b << 10) + j]) + EPSF;
        float v = c * c * c / (am * bm);
        if (mask[(b << 10) + j] != 0) v = 1e-4f;
        v *= 3.0f;
        vals[j] = v;
        lm = fmaxf(lm, v);
    }
    red[tid] = lm; __syncthreads();
    for (int s = 128; s > 0; s >>= 1) {
        if (tid < s) red[tid] = fmaxf(red[tid], red[tid + s]);
        __syncthreads();
    }
    float m = red[0];
    __syncthreads();
    float ls = 0.f;
    for (int j = tid; j < HWD; j += 256) {
        float e = __expf(vals[j] - m);
        vals[j] = e;
        ls += e;
    }
    red[tid] = ls; __syncthreads();
    for (int s = 128; s > 0; s >>= 1) {
        if (tid < s) red[tid] += red[tid + s];
        __syncthreads();
    }
    float inv = 1.f / red[0];
    __syncthreads();
    for (int j = tid; j < HWD; j += 256)
        g_attn[base + j] = vals[j] * inv;
}

// ---------------- out[b,c,q] = sum_k v[b,c,k] * attn[b,q,k] ----------------
__global__ void __launch_bounds__(256) gemm_kernel(const float* __restrict__ v,
                                                   float* __restrict__ out) {
    __shared__ __align__(16) float Vs[16][68];
    __shared__ __align__(16) float As[16][68];
    int b = blockIdx.z;
    int cT = blockIdx.x * 64;
    int qT = blockIdx.y * 64;
    int tid = threadIdx.x;
    int tx = tid & 15, ty = tid >> 4;
    ull acc2[4][2];
    #pragma unroll
    for (int i = 0; i < 4; i++) { acc2[i][0] = 0ull; acc2[i][1] = 0ull; }
    const float* vb = v + (size_t)b * 256 * 1024;
    const float* ab = g_attn + (size_t)b * HWD * HWD;
    for (int k0 = 0; k0 < 1024; k0 += 16) {
        #pragma unroll
        for (int i = 0; i < 4; i++) {
            int idx = tid + i * 256;
            int kk = idx & 15, cc = idx >> 4;
            Vs[kk][cc] = vb[(size_t)(cT + cc) * 1024 + k0 + kk];
            As[kk][cc] = ab[(size_t)(qT + cc) * HWD + k0 + kk];
        }
        __syncthreads();
        #pragma unroll
        for (int kk = 0; kk < 16; kk++) {
            float4 a4 = *(const float4*)&Vs[kk][ty * 4];
            const ull* bp = (const ull*)&As[kk][tx * 4];
            ull b0 = bp[0], b1 = bp[1];
            float a[4] = {a4.x, a4.y, a4.z, a4.w};
            #pragma unroll
            for (int i = 0; i < 4; i++) {
                ull ad; PACK2(ad, a[i], a[i]);
                FMA2(acc2[i][0], b0, ad);
                FMA2(acc2[i][1], b1, ad);
            }
        }
        __syncthreads();
    }
    #pragma unroll
    for (int i = 0; i < 4; i++) {
        float r0, r1, r2, r3;
        UNPACK2(r0, r1, acc2[i][0]);
        UNPACK2(r2, r3, acc2[i][1]);
        *(float4*)(out + (size_t)(b * 256 + cT + ty * 4 + i) * 1024 + qT + tx * 4)
            = make_float4(r0, r1, r2, r3);
    }
}

// ---------------- host launch ----------------
static inline int fconv_smem(int Ci, int Co, int COG, int W) {
    int cpg = Co / COG, kp = (cpg + 1) / 2;
    int nw4 = Ci * 9 * COG * kp;
    return 2 * nw4 * 16 + ((Co + 3) & ~3) * 4 + 3 * (W + 2) * SLICE * 4;
}

extern "C" void kernel_launch(void* const* d_in, const int* in_sizes, int n_in,
                              void* d_out, int out_size) {
    const float* corr = (const float*)d_in[0];
    const float* v    = (const float*)d_in[1];
    const int*   mask = (const int*)d_in[2];
    const float* wq[3] = {(const float*)d_in[3],  (const float*)d_in[7],  (const float*)d_in[11]};
    const float* bq[3] = {(const float*)d_in[4],  (const float*)d_in[8],  (const float*)d_in[12]};
    const float* ws[3] = {(const float*)d_in[5],  (const float*)d_in[9],  (const float*)d_in[13]};
    const float* bs[3] = {(const float*)d_in[6],  (const float*)d_in[10], (const float*)d_in[14]};
    float* out = (float*)d_out;

    float *p_mm, *p_mmT, *p_P, *p_Q, *p_P2, *p_Q2, *p_y1, *p_zT, *p_cf, *p_amax;
    cudaGetSymbolAddress((void**)&p_mm,  g_mm);
    cudaGetSymbolAddress((void**)&p_mmT, g_mmT);
    cudaGetSymbolAddress((void**)&p_P,   g_P);
    cudaGetSymbolAddress((void**)&p_Q,   g_Q);
    cudaGetSymbolAddress((void**)&p_P2,  g_P2);
    cudaGetSymbolAddress((void**)&p_Q2,  g_Q2);
    cudaGetSymbolAddress((void**)&p_y1,  g_y1);
    cudaGetSymbolAddress((void**)&p_zT,  g_zT);
    cudaGetSymbolAddress((void**)&p_cf,  g_cf);
    cudaGetSymbolAddress((void**)&p_amax, g_amax);

    const int sm110  = fconv_smem(1, 10, 1, 1);
    const int sm1010 = fconv_smem(10, 10, 1, 1);
    const int sm101  = fconv_smem(10, 1, 1, 4);
    cudaFuncSetAttribute((fconv_kernel<1, 10, 1, 1, 256, 3>),
                         cudaFuncAttributeMaxDynamicSharedMemorySize, sm110);
    cudaFuncSetAttribute((fconv_kernel<10, 10, 1, 1, 256, 3>),
                         cudaFuncAttributeMaxDynamicSharedMemorySize, sm1010);
    cudaFuncSetAttribute((fconv_kernel<10, 1, 1, 4, 256, 2>),
                         cudaFuncAttributeMaxDynamicSharedMemorySize, sm101);

    dim3 tile32(32, 8);
    dim3 gridTiles(32, 32, Bb);

    // ---- mutual matching #1 (fused single-pass row+col maxes) ----
    initb_kernel<<<16, 256>>>();
    rowcolmax_kernel<<<dim3(8, Bb), 256>>>(corr, p_amax);
    mm_kernel<<<gridTiles, tile32>>>(corr);

    // ---- both symmetric stacks per layer in one launch (gridDim.y = 2) ----
    fconv_kernel<1, 10, 1, 1, 256, 3> <<<dim3(Bb * 1024, 2), 256, sm110 >>>(
        p_mm, p_mmT, wq[0], bq[0], ws[0], bs[0], p_P, p_P2);
    fconv_kernel<10, 10, 1, 1, 256, 3><<<dim3(Bb * 1024, 2), 256, sm1010>>>(
        p_P, p_P2, wq[1], bq[1], ws[1], bs[1], p_Q, p_Q2);
    fconv_kernel<10, 1, 1, 4, 256, 2> <<<dim3(Bb * 256, 2),  256, sm101 >>>(
        p_Q, p_Q2, wq[2], bq[2], ws[2], bs[2], p_y1, p_zT);

    // ---- cf = y1 + T(zT) fused with phase-2 maxes ----
    initab_kernel<<<16, 256>>>();
    transadd_kernel<<<gridTiles, tile32>>>(p_y1, p_zT, p_cf);

    // ---- masked softmax ----
    softmax_kernel<<<Bb * HWD, 256>>>(p_cf, mask);

    // ---- weighted sum: out = v @ attn^T ----
    gemm_kernel<<<dim3(4, 16, Bb), 256>>>(v, out);
}

// round 16
// speedup vs baseline: 1.1890x; 1.0534x over previous
#include <cuda_runtime.h>
#include <cuda_bf16.h>
#include <cstdint>

#define Bb 4
#define HWD 1024
#define EPSF 1e-5f

#define SSTR 36            // padded row stride (floats); 144 B => 16B-aligned rows
#define SLICE (32 * SSTR)  // 1152 floats per staged 32x32 slice

typedef unsigned long long ull;

// ---------------- scratch ----------------
__device__ float g_mm  [(size_t)Bb*HWD*HWD];
__device__ float g_mmT [(size_t)Bb*HWD*HWD];
__device__ float g_P   [(size_t)Bb*10*HWD*HWD];
__device__ float g_Q   [(size_t)Bb*10*HWD*HWD];
__device__ float g_P2  [(size_t)Bb*10*HWD*HWD];
__device__ float g_Q2  [(size_t)Bb*10*HWD*HWD];
__device__ float g_y1  [(size_t)Bb*HWD*HWD];
__device__ float g_zT  [(size_t)Bb*HWD*HWD];
__device__ float g_cf  [(size_t)Bb*HWD*HWD];
__device__ float g_attn[(size_t)Bb*HWD*HWD];
__device__ float    g_amax  [Bb*HWD];
__device__ unsigned g_amaxu2[Bb*HWD];
__device__ unsigned g_bmaxu [Bb*HWD];

// ---------------- helpers ----------------
__device__ __forceinline__ unsigned enc_f(float f) {
    unsigned u = __float_as_uint(f);
    return (u & 0x80000000u) ? ~u : (u | 0x80000000u);
}
__device__ __forceinline__ float dec_f(unsigned u) {
    return __uint_as_float((u & 0x80000000u) ? (u & 0x7fffffffu) : ~u);
}

#define PACK2(p, lo, hi)  asm("mov.b64 %0, {%1, %2};" : "=l"(p) : "f"(lo), "f"(hi))
#define UNPACK2(lo, hi, p) asm("mov.b64 {%0, %1}, %2;" : "=f"(lo), "=f"(hi) : "l"(p))
#define FMA2(d, a, w)     asm("fma.rn.f32x2 %0, %1, %2, %3;" : "=l"(d) : "l"(a), "l"(w), "l"(d))

// ---------------- init / max reductions ----------------
__global__ void initb_kernel() {
    int i = blockIdx.x * blockDim.x + threadIdx.x;
    if (i < Bb * HWD) g_bmaxu[i] = 0u;
}
__global__ void initab_kernel() {
    int i = blockIdx.x * blockDim.x + threadIdx.x;
    if (i < Bb * HWD) { g_bmaxu[i] = 0u; g_amaxu2[i] = 0u; }
}

__global__ void rowmax_kernel(const float* __restrict__ p1, float* __restrict__ om) {
    int row = blockIdx.x;
    size_t base = (size_t)row * HWD;
    int tid = threadIdx.x;
    float m = -3.4e38f;
    for (int j = tid; j < HWD; j += 256) m = fmaxf(m, p1[base + j]);
    __shared__ float red[256];
    red[tid] = m; __syncthreads();
    for (int s = 128; s > 0; s >>= 1) {
        if (tid < s) red[tid] = fmaxf(red[tid], red[tid + s]);
        __syncthreads();
    }
    if (tid == 0) om[row] = red[0];
}

__global__ void colmax_kernel(const float* __restrict__ p1) {
    int chunk = blockIdx.x;
    int b = blockIdx.y;
    int i0 = threadIdx.x * 4;
    size_t bb = (size_t)b * HWD * HWD;
    float m0 = -3.4e38f, m1 = -3.4e38f, m2 = -3.4e38f, m3 = -3.4e38f;
    int oBeg = chunk * 128, oEnd = oBeg + 128;
    for (int o = oBeg; o < oEnd; o++) {
        const float4 v = *(const float4*)(p1 + bb + (size_t)o * HWD + i0);
        m0 = fmaxf(m0, v.x); m1 = fmaxf(m1, v.y);
        m2 = fmaxf(m2, v.z); m3 = fmaxf(m3, v.w);
    }
    int ib = b * HWD + i0;
    atomicMax(&g_bmaxu[ib + 0], enc_f(m0));
    atomicMax(&g_bmaxu[ib + 1], enc_f(m1));
    atomicMax(&g_bmaxu[ib + 2], enc_f(m2));
    atomicMax(&g_bmaxu[ib + 3], enc_f(m3));
}

// ---------------- mutual matching #1 ----------------
__global__ void mm_kernel(const float* __restrict__ corr) {
    int to = blockIdx.x, ti = blockIdx.y;
    if (ti < to) return;
    int b = blockIdx.z;
    size_t base = (size_t)b * HWD * HWD;
    __shared__ float s1[32][33], s2[32][33];
    int tx = threadIdx.x, ty0 = threadIdx.y;
    #pragma unroll
    for (int k = 0; k < 4; k++) {
        int y = ty0 + k * 8;
        int o1 = to * 32 + y, i1 = ti * 32 + tx;
        float c1 = corr[base + (size_t)o1 * HWD + i1];
        float v1 = c1 * c1 * c1 /
                   ((g_amax[b * HWD + o1] + EPSF) * (dec_f(g_bmaxu[b * HWD + i1]) + EPSF));
        g_mm[base + (size_t)o1 * HWD + i1] = v1;
        s1[y][tx] = v1;
        int o2 = ti * 32 + y, i2 = to * 32 + tx;
        float c2 = corr[base + (size_t)o2 * HWD + i2];
        float v2 = c2 * c2 * c2 /
                   ((g_amax[b * HWD + o2] + EPSF) * (dec_f(g_bmaxu[b * HWD + i2]) + EPSF));
        g_mm[base + (size_t)o2 * HWD + i2] = v2;
        s2[y][tx] = v2;
    }
    __syncthreads();
    #pragma unroll
    for (int k = 0; k < 4; k++) {
        int y = ty0 + k * 8;
        g_mmT[base + (size_t)(to * 32 + y) * HWD + ti * 32 + tx] = s2[tx][y];
        g_mmT[base + (size_t)(ti * 32 + y) * HWD + to * 32 + tx] = s1[tx][y];
    }
}

// ---------------- lean layer-1 kernel (Ci=1, Co=10): direct-global streaming -----
// No slice staging: weights in smem (one sync), operands read straight from
// global (L2-resident input), outputs streamed. Write-bandwidth bound.
__global__ void __launch_bounds__(256) fconv1_kernel(
    const float* __restrict__ in0, const float* __restrict__ in1,
    const float* __restrict__ wq, const float* __restrict__ bq,
    const float* __restrict__ wsp, const float* __restrict__ bsp,
    float* __restrict__ out0, float* __restrict__ out1)
{
    __shared__ ulonglong2 wq4[45], ws4[45];   // KP=5 pairs x 9 taps
    __shared__ float bsum[12];
    int tid = threadIdx.x;
    if (tid < 90) {
        int r = tid % 45;
        const float* wsrc = (tid < 45) ? wq : wsp;
        ulonglong2* wdst  = (tid < 45) ? wq4 : ws4;
        int k = r % 5, tp = r / 5;
        float a0 = wsrc[(2 * k) * 9 + tp];
        float a1 = wsrc[(2 * k + 1) * 9 + tp];
        ull p0, p1; PACK2(p0, a0, a0); PACK2(p1, a1, a1);
        wdst[r] = make_ulonglong2(p0, p1);
    }
    if (tid < 10) bsum[tid] = bq[tid] + bsp[tid];
    __syncthreads();

    const float* in  = blockIdx.y ? in1  : in0;
    float*       out = blockIdx.y ? out1 : out0;
    int blk = blockIdx.x;
    int b = blk >> 10;
    int o = blk & 1023;
    int h = o >> 5, w0 = o & 31;
    int py  = tid >> 3;             // 0..31
    int px0 = (tid & 7) * 4;        // 0,4,...,28

    size_t base = (size_t)b << 20;
    const float* ctr = in + base + ((size_t)o << 10);

    ull acc[10][2];
    #pragma unroll
    for (int co = 0; co < 10; co++) { acc[co][0] = 0ull; acc[co][1] = 0ull; }

    // ---- inner 3x3 conv on the center slice (direct global reads) ----
    #pragma unroll
    for (int dy = 0; dy < 3; dy++) {
        int gy = py + dy - 1;
        float t[6];
        if ((unsigned)gy < 32u) {
            const float* cr = ctr + gy * 32;
            float4 vv = *(const float4*)(cr + px0);
            t[1] = vv.x; t[2] = vv.y; t[3] = vv.z; t[4] = vv.w;
            t[0] = (px0 > 0)      ? cr[px0 - 1] : 0.f;
            t[5] = (px0 + 4 < 32) ? cr[px0 + 4] : 0.f;
        } else {
            #pragma unroll
            for (int j = 0; j < 6; j++) t[j] = 0.f;
        }
        ull pr[5];
        #pragma unroll
        for (int i = 0; i < 5; i++) PACK2(pr[i], t[i], t[i + 1]);
        #pragma unroll
        for (int dx = 0; dx < 3; dx++) {
            const ulonglong2* wp = ws4 + (dy * 3 + dx) * 5;
            #pragma unroll
            for (int k = 0; k < 5; k++) {
                ulonglong2 wv = wp[k];
                FMA2(acc[2 * k][0],     pr[dx],     wv.x);
                FMA2(acc[2 * k][1],     pr[dx + 2], wv.x);
                FMA2(acc[2 * k + 1][0], pr[dx],     wv.y);
                FMA2(acc[2 * k + 1][1], pr[dx + 2], wv.y);
            }
        }
    }
    // ---- outer 3x3 conv: same pixels from the 9 neighbor slices ----
    #pragma unroll
    for (int ky = 0; ky < 3; ky++) {
        #pragma unroll
        for (int kx = 0; kx < 3; kx++) {
            int ny = h - 1 + ky, nx = w0 - 1 + kx;
            ull u0 = 0ull, u1 = 0ull;
            if ((unsigned)ny < 32u && (unsigned)nx < 32u) {
                float4 vv = *(const float4*)(in + base
                    + ((size_t)(ny * 32 + nx) << 10) + py * 32 + px0);
                PACK2(u0, vv.x, vv.y);
                PACK2(u1, vv.z, vv.w);
            }
            const ulonglong2* wp = wq4 + (ky * 3 + kx) * 5;
            #pragma unroll
            for (int k = 0; k < 5; k++) {
                ulonglong2 wv = wp[k];
                FMA2(acc[2 * k][0],     u0, wv.x);
                FMA2(acc[2 * k][1],     u1, wv.x);
                FMA2(acc[2 * k + 1][0], u0, wv.y);
                FMA2(acc[2 * k + 1][1], u1, wv.y);
            }
        }
    }

    // ---- epilogue: bias + relu, streamed float4 stores ----
    #pragma unroll
    for (int co = 0; co < 10; co++) {
        float bsc = bsum[co];
        float o0, o1v, o2, o3;
        UNPACK2(o0, o1v, acc[co][0]);
        UNPACK2(o2, o3,  acc[co][1]);
        o0 = fmaxf(o0 + bsc, 0.f); o1v = fmaxf(o1v + bsc, 0.f);
        o2 = fmaxf(o2 + bsc, 0.f); o3  = fmaxf(o3 + bsc, 0.f);
        *(float4*)(out + (((size_t)(b * 10 + co)) << 20) + ((size_t)o << 10)
                   + py * 32 + px0) = make_float4(o0, o1v, o2, o3);
    }
}

// ---------------- fused CenterPivotConv4d layer (R12 best config) ----------------
template <int Ci, int Co, int COG, int W, int THREADS, int MINB>
__global__ void __launch_bounds__(THREADS, MINB) fconv_kernel(
    const float* __restrict__ in0, const float* __restrict__ in1,
    const float* __restrict__ wq, const float* __restrict__ bq,
    const float* __restrict__ wsp, const float* __restrict__ bsp,
    float* __restrict__ out0, float* __restrict__ out1)
{
    constexpr int R   = 3 * (W + 2);
    constexpr int CPG = Co / COG;
    constexpr int KP  = (CPG + 1) / 2;
    constexpr int NW4 = Ci * 9 * COG * KP;
    constexpr int TPG = THREADS / COG;
    constexpr int TPC = TPG / W;
    constexpr int PPT = 1024 / TPC;
    constexpr int RP  = PPT / 2;
    constexpr int LPR = TPC / 32;
    static_assert(PPT % 4 == 0, "PPT must be multiple of 4");

    extern __shared__ unsigned char smraw[];
    ulonglong2* wq4 = (ulonglong2*)smraw;
    ulonglong2* ws4 = wq4 + NW4;
    float* bsum = (float*)(ws4 + NW4);
    float* rows = bsum + ((Co + 3) & ~3);

    const float* in  = blockIdx.y ? in1  : in0;
    float*       out = blockIdx.y ? out1 : out0;
    int tid = threadIdx.x;

    for (int idx = tid; idx < 2 * NW4; idx += THREADS) {
        int r = idx % NW4;
        const float* wsrc = (idx < NW4) ? wq : wsp;
        ulonglong2* wdst  = (idx < NW4) ? wq4 : ws4;
        int k  = r % KP;
        int g  = (r / KP) % COG;
        int tp = (r / (KP * COG)) % 9;
        int ci = r / (KP * COG * 9);
        int co0 = g * CPG + 2 * k;
        int co1 = co0 + 1; if (co1 > g * CPG + CPG - 1) co1 = co0;
        float a0 = wsrc[(co0 * Ci + ci) * 9 + tp];
        float a1 = wsrc[(co1 * Ci + ci) * 9 + tp];
        ull p0, p1; PACK2(p0, a0, a0); PACK2(p1, a1, a1);
        wdst[r] = make_ulonglong2(p0, p1);
    }
    if (tid < Co) bsum[tid] = bq[tid] + bsp[tid];

    constexpr int BPB = 1024 / W;
    int blk = blockIdx.x;
    int b   = blk / BPB;
    int rem = blk - b * BPB;
    int h   = rem / (32 / W);
    int w0  = (rem - h * (32 / W)) * W;

    int cgrp = tid / TPG;
    int lt   = tid % TPG;
    int c    = lt / TPC;
    int sub  = lt % TPC;
    int py   = sub / LPR;
    int px0  = (sub % LPR) * PPT;

    ull acc[CPG][RP];
    #pragma unroll
    for (int l = 0; l < CPG; l++)
        #pragma unroll
        for (int rp = 0; rp < RP; rp++) acc[l][rp] = 0ull;

    for (int ci = 0; ci < Ci; ci++) {
        __syncthreads();
        size_t cBase = ((size_t)(b * Ci + ci)) << 20;
        for (int idx = tid; idx < R * 256; idx += THREADS) {
            int k = idx >> 8; int j = idx & 255;
            int ry = k / (W + 2); int rx = k - ry * (W + 2);
            int ny = h - 1 + ry, nx = w0 - 1 + rx;
            float4 v = make_float4(0.f, 0.f, 0.f, 0.f);
            if ((unsigned)ny < 32u && (unsigned)nx < 32u)
                v = *(const float4*)(in + cBase + ((size_t)(ny * 32 + nx) << 10) + (j << 2));
            int irow = j >> 3, icol = (j & 7) << 2;
            *(float4*)(rows + k * SLICE + irow * SSTR + icol) = v;   // STS.128
        }
        __syncthreads();

        const float* cr0 = rows + ((W + 2) + (c + 1)) * SLICE;
        #pragma unroll
        for (int dy = 0; dy < 3; dy++) {
            int iy = py + dy - 1;
            float t[PPT + 2];
            if ((unsigned)iy < 32u) {
                const float* cr = cr0 + iy * SSTR;
                #pragma unroll
                for (int q = 0; q < PPT / 4; q++) {
                    float4 vv = *(const float4*)(cr + px0 + 4 * q);   // LDS.128
                    t[1 + 4 * q] = vv.x; t[2 + 4 * q] = vv.y;
                    t[3 + 4 * q] = vv.z; t[4 + 4 * q] = vv.w;
                }
                t[0]       = (px0 > 0)        ? cr[px0 - 1]   : 0.f;
                t[PPT + 1] = (px0 + PPT < 32) ? cr[px0 + PPT] : 0.f;
            } else {
                #pragma unroll
                for (int jj = 0; jj < PPT + 2; jj++) t[jj] = 0.f;
            }
            ull pr[PPT + 1];
            #pragma unroll
            for (int i = 0; i < PPT + 1; i++) PACK2(pr[i], t[i], t[i + 1]);
            #pragma unroll
            for (int dx = 0; dx < 3; dx++) {
                const ulonglong2* wp = ws4 + ((ci * 9 + dy * 3 + dx) * COG + cgrp) * KP;
                #pragma unroll
                for (int k = 0; k < KP; k++) {
                    ulonglong2 wv = wp[k];
                    #pragma unroll
                    for (int rp = 0; rp < RP; rp++)
                        FMA2(acc[2 * k][rp], pr[dx + 2 * rp], wv.x);
                    if (2 * k + 1 < CPG) {
                        #pragma unroll
                        for (int rp = 0; rp < RP; rp++)
                            FMA2(acc[2 * k + 1][rp], pr[dx + 2 * rp], wv.y);
                    }
                }
            }
        }
        #pragma unroll
        for (int ky = 0; ky < 3; ky++) {
            #pragma unroll
            for (int kx = 0; kx < 3; kx++) {
                const ulonglong2* up = (const ulonglong2*)(rows
                    + (ky * (W + 2) + c + kx) * SLICE + py * SSTR + px0);
                ull u[RP];
                #pragma unroll
                for (int rp = 0; rp < RP; rp += 2) {
                    ulonglong2 uu = up[rp >> 1];                      // LDS.128
                    u[rp] = uu.x; u[rp + 1] = uu.y;
                }
                const ulonglong2* wp = wq4 + ((ci * 9 + ky * 3 + kx) * COG + cgrp) * KP;
                #pragma unroll
                for (int k = 0; k < KP; k++) {
                    ulonglong2 wv = wp[k];
                    #pragma unroll
                    for (int rp = 0; rp < RP; rp++)
                        FMA2(acc[2 * k][rp], u[rp], wv.x);
                    if (2 * k + 1 < CPG) {
                        #pragma unroll
                        for (int rp = 0; rp < RP; rp++)
                            FMA2(acc[2 * k + 1][rp], u[rp], wv.y);
                    }
                }
            }
        }
    }

    #pragma unroll
    for (int l = 0; l < CPG; l++) {
        int co = cgrp * CPG + l;
        float bsc = bsum[co];
        float o[PPT];
        #pragma unroll
        for (int rp = 0; rp < RP; rp++) {
            float lo, hi; UNPACK2(lo, hi, acc[l][rp]);
            o[2 * rp]     = fmaxf(lo + bsc, 0.f);
            o[2 * rp + 1] = fmaxf(hi + bsc, 0.f);
        }
        float* ob = out + (((size_t)(b * Co + co)) << 20)
                    + ((size_t)(h * 32 + w0 + c) << 10) + py * 32 + px0;
        #pragma unroll
        for (int q = 0; q < PPT; q += 4)
            *(float4*)(ob + q) = make_float4(o[q], o[q + 1], o[q + 2], o[q + 3]);
    }
}

// ---------------- cf = y1 + T(zT), fused with phase-2 row/col maxes ----------------
__global__ void transadd_kernel(const float* __restrict__ y1, const float* __restrict__ zT,
                                float* __restrict__ cf) {
    int to = blockIdx.x, ti = blockIdx.y, b = blockIdx.z;
    size_t base = (size_t)b << 20;
    __shared__ float s[32][33];
    __shared__ unsigned cred[8][32];
    int tx = threadIdx.x, ty0 = threadIdx.y;
    #pragma unroll
    for (int k = 0; k < 4; k++) {
        int y = ty0 + k * 8;
        s[y][tx] = zT[base + ((size_t)(ti * 32 + y) << 10) + to * 32 + tx];
    }
    __syncthreads();
    float v[4];
    #pragma unroll
    for (int k = 0; k < 4; k++) {
        int y = ty0 + k * 8;
        size_t idx = base + ((size_t)(to * 32 + y) << 10) + ti * 32 + tx;
        v[k] = y1[idx] + s[tx][y];
        cf[idx] = v[k];
    }
    #pragma unroll
    for (int k = 0; k < 4; k++) {
        float m = v[k];
        #pragma unroll
        for (int off = 16; off; off >>= 1)
            m = fmaxf(m, __shfl_xor_sync(0xffffffffu, m, off));
        if (tx == 0)
            atomicMax(&g_amaxu2[b * HWD + to * 32 + ty0 + k * 8], enc_f(m));
    }
    float cm = fmaxf(fmaxf(v[0], v[1]), fmaxf(v[2], v[3]));
    cred[ty0][tx] = enc_f(cm);
    __syncthreads();
    if (ty0 == 0) {
        unsigned m = cred[0][tx];
        #pragma unroll
        for (int w = 1; w < 8; w++) m = max(m, cred[w][tx]);
        atomicMax(&g_bmaxu[b * HWD + ti * 32 + tx], m);
    }
}

// ---------------- mutual matching #2 + mask + softmax ----------------
__global__ void softmax_kernel(const float* __restrict__ cf, const int* __restrict__ mask) {
    int row = blockIdx.x;
    int b = row >> 10;
    size_t base = (size_t)row * HWD;
    __shared__ float vals[1024];
    __shared__ float red[256];
    int tid = threadIdx.x;
    float am = dec_f(g_amaxu2[row]) + EPSF;
    float lm = -3.4e38f;
    for (int j = tid; j < HWD; j += 256) {
        float c = cf[base + j];
        float bm = dec_f(g_bmaxu[(b << 10) + j]) + EPSF;
        float v = c * c * c / (am * bm);
        if (mask[(b << 10) + j] != 0) v = 1e-4f;
        v *= 3.0f;
        vals[j] = v;
        lm = fmaxf(lm, v);
    }
    red[tid] = lm; __syncthreads();
    for (int s = 128; s > 0; s >>= 1) {
        if (tid < s) red[tid] = fmaxf(red[tid], red[tid + s]);
        __syncthreads();
    }
    float m = red[0];
    __syncthreads();
    float ls = 0.f;
    for (int j = tid; j < HWD; j += 256) {
        float e = __expf(vals[j] - m);
        vals[j] = e;
        ls += e;
    }
    red[tid] = ls; __syncthreads();
    for (int s = 128; s > 0; s >>= 1) {
        if (tid < s) red[tid] += red[tid + s];
        __syncthreads();
    }
    float inv = 1.f / red[0];
    __syncthreads();
    for (int j = tid; j < HWD; j += 256)
        g_attn[base + j] = vals[j] * inv;
}

// ---------------- out[b,c,q] = sum_k v[b,c,k] * attn[b,q,k] ----------------
__global__ void __launch_bounds__(256) gemm_kernel(const float* __restrict__ v,
                                                   float* __restrict__ out) {
    __shared__ __align__(16) float Vs[16][68];
    __shared__ __align__(16) float As[16][68];
    int b = blockIdx.z;
    int cT = blockIdx.x * 64;
    int qT = blockIdx.y * 64;
    int tid = threadIdx.x;
    int tx = tid & 15, ty = tid >> 4;
    ull acc2[4][2];
    #pragma unroll
    for (int i = 0; i < 4; i++) { acc2[i][0] = 0ull; acc2[i][1] = 0ull; }
    const float* vb = v + (size_t)b * 256 * 1024;
    const float* ab = g_attn + (size_t)b * HWD * HWD;
    for (int k0 = 0; k0 < 1024; k0 += 16) {
        #pragma unroll
        for (int i = 0; i < 4; i++) {
            int idx = tid + i * 256;
            int kk = idx & 15, cc = idx >> 4;
            Vs[kk][cc] = vb[(size_t)(cT + cc) * 1024 + k0 + kk];
            As[kk][cc] = ab[(size_t)(qT + cc) * HWD + k0 + kk];
        }
        __syncthreads();
        #pragma unroll
        for (int kk = 0; kk < 16; kk++) {
            float4 a4 = *(const float4*)&Vs[kk][ty * 4];
            const ull* bp = (const ull*)&As[kk][tx * 4];
            ull b0 = bp[0], b1 = bp[1];
            float a[4] = {a4.x, a4.y, a4.z, a4.w};
            #pragma unroll
            for (int i = 0; i < 4; i++) {
                ull ad; PACK2(ad, a[i], a[i]);
                FMA2(acc2[i][0], b0, ad);
                FMA2(acc2[i][1], b1, ad);
            }
        }
        __syncthreads();
    }
    #pragma unroll
    for (int i = 0; i < 4; i++) {
        float r0, r1, r2, r3;
        UNPACK2(r0, r1, acc2[i][0]);
        UNPACK2(r2, r3, acc2[i][1]);
        *(float4*)(out + (size_t)(b * 256 + cT + ty * 4 + i) * 1024 + qT + tx * 4)
            = make_float4(r0, r1, r2, r3);
    }
}

// ---------------- host launch ----------------
static inline int fconv_smem(int Ci, int Co, int COG, int W) {
    int cpg = Co / COG, kp = (cpg + 1) / 2;
    int nw4 = Ci * 9 * COG * kp;
    return 2 * nw4 * 16 + ((Co + 3) & ~3) * 4 + 3 * (W + 2) * SLICE * 4;
}

extern "C" void kernel_launch(void* const* d_in, const int* in_sizes, int n_in,
                              void* d_out, int out_size) {
    const float* corr = (const float*)d_in[0];
    const float* v    = (const float*)d_in[1];
    const int*   mask = (const int*)d_in[2];
    const float* wq[3] = {(const float*)d_in[3],  (const float*)d_in[7],  (const float*)d_in[11]};
    const float* bq[3] = {(const float*)d_in[4],  (const float*)d_in[8],  (const float*)d_in[12]};
    const float* ws[3] = {(const float*)d_in[5],  (const float*)d_in[9],  (const float*)d_in[13]};
    const float* bs[3] = {(const float*)d_in[6],  (const float*)d_in[10], (const float*)d_in[14]};
    float* out = (float*)d_out;

    float *p_mm, *p_mmT, *p_P, *p_Q, *p_P2, *p_Q2, *p_y1, *p_zT, *p_cf, *p_amax;
    cudaGetSymbolAddress((void**)&p_mm,  g_mm);
    cudaGetSymbolAddress((void**)&p_mmT, g_mmT);
    cudaGetSymbolAddress((void**)&p_P,   g_P);
    cudaGetSymbolAddress((void**)&p_Q,   g_Q);
    cudaGetSymbolAddress((void**)&p_P2,  g_P2);
    cudaGetSymbolAddress((void**)&p_Q2,  g_Q2);
    cudaGetSymbolAddress((void**)&p_y1,  g_y1);
    cudaGetSymbolAddress((void**)&p_zT,  g_zT);
    cudaGetSymbolAddress((void**)&p_cf,  g_cf);
    cudaGetSymbolAddress((void**)&p_amax, g_amax);

    const int sm1010 = fconv_smem(10, 10, 1, 1);
    const int sm101  = fconv_smem(10, 1, 1, 4);
    cudaFuncSetAttribute((fconv_kernel<10, 10, 1, 1, 256, 3>),
                         cudaFuncAttributeMaxDynamicSharedMemorySize, sm1010);
    cudaFuncSetAttribute((fconv_kernel<10, 1, 1, 4, 256, 2>),
                         cudaFuncAttributeMaxDynamicSharedMemorySize, sm101);

    dim3 tile32(32, 8);
    dim3 gridTiles(32, 32, Bb);

    // ---- mutual matching #1 ----
    initb_kernel<<<16, 256>>>();
    rowmax_kernel<<<Bb * HWD, 256>>>(corr, p_amax);
    colmax_kernel<<<dim3(8, Bb), 256>>>(corr);
    mm_kernel<<<gridTiles, tile32>>>(corr);

    // ---- both symmetric stacks per layer in one launch (gridDim.y = 2) ----
    fconv1_kernel<<<dim3(Bb * 1024, 2), 256>>>(
        p_mm, p_mmT, wq[0], bq[0], ws[0], bs[0], p_P, p_P2);
    fconv_kernel<10, 10, 1, 1, 256, 3><<<dim3(Bb * 1024, 2), 256, sm1010>>>(
        p_P, p_P2, wq[1], bq[1], ws[1], bs[1], p_Q, p_Q2);
    fconv_kernel<10, 1, 1, 4, 256, 2> <<<dim3(Bb * 256, 2),  256, sm101 >>>(
        p_Q, p_Q2, wq[2], bq[2], ws[2], bs[2], p_y1, p_zT);

    // ---- cf = y1 + T(zT) fused with phase-2 maxes ----
    initab_kernel<<<16, 256>>>();
    transadd_kernel<<<gridTiles, tile32>>>(p_y1, p_zT, p_cf);

    // ---- masked softmax ----
    softmax_kernel<<<Bb * HWD, 256>>>(p_cf, mask);

    // ---- weighted sum: out = v @ attn^T ----
    gemm_kernel<<<dim3(4, 16, Bb), 256>>>(v, out);
}